// round 4
// baseline (speedup 1.0000x reference)
#include <cuda_runtime.h>
#include <cstdint>

#define T_LEN 65536
#define H 108
#define G4 432
#define NGATE 864       // 108 j-units x 8 K-chunks
#define NTHR 896        // + 1 scalar warp
#define KC 14           // K-extent per thread (8*14 = 112 >= 108, zero-padded)

// ---------------- device scratch ----------------
__device__ float g_imp[2][T_LEN];
__device__ float g_loss[2];
__device__ float g_part[256];

// ---------------- f32x2 helpers ----------------
__device__ __forceinline__ void fma2(unsigned long long &acc, unsigned long long a, unsigned long long b) {
    asm volatile("fma.rn.f32x2 %0, %1, %2, %0;" : "+l"(acc) : "l"(a), "l"(b));
}
__device__ __forceinline__ unsigned long long pk2(float a, float b) {
    unsigned long long r;
    asm("mov.b64 %0, {%1, %2};" : "=l"(r) : "f"(a), "f"(b));
    return r;
}
__device__ __forceinline__ float2 upk(unsigned long long v) {
    float2 r;
    asm("mov.b64 {%0, %1}, %2;" : "=f"(r.x), "=f"(r.y) : "l"(v));
    return r;
}
__device__ __forceinline__ float tanh_fast(float x) {
    float y;
    asm("tanh.approx.f32 %0, %1;" : "=f"(y) : "f"(x));
    return y;
}
__device__ __forceinline__ float sigmoid_fast(float x) {
    return fmaf(tanh_fast(0.5f * x), 0.5f, 0.5f);
}

// ---------------- main recurrence: one block per direction ----------------
__global__ void __launch_bounds__(NTHR, 1) brits_kernel(
    const float* __restrict__ values,  const float* __restrict__ masks,
    const float* __restrict__ deltas_f, const float* __restrict__ deltas_b,
    const float* __restrict__ f_td_w,  const float* __restrict__ f_td_b,
    const float* __restrict__ f_reg_w, const float* __restrict__ f_reg_b,
    const float* __restrict__ f_W_ih,  const float* __restrict__ f_W_hh,
    const float* __restrict__ f_b_ih,  const float* __restrict__ f_b_hh,
    const float* __restrict__ b_td_w,  const float* __restrict__ b_td_b,
    const float* __restrict__ b_reg_w, const float* __restrict__ b_reg_b,
    const float* __restrict__ b_W_ih,  const float* __restrict__ b_W_hh,
    const float* __restrict__ b_b_ih,  const float* __restrict__ b_b_hh)
{
    const int dir = blockIdx.x;
    const float* td_w  = dir ? b_td_w  : f_td_w;
    const float* td_b  = dir ? b_td_b  : f_td_b;
    const float* reg_w = dir ? b_reg_w : f_reg_w;
    const float* reg_b = dir ? b_reg_b : f_reg_b;
    const float* W_ih  = dir ? b_W_ih  : f_W_ih;
    const float* W_hh  = dir ? b_W_hh  : f_W_hh;
    const float* b_ih  = dir ? b_b_ih  : f_b_ih;
    const float* b_hh  = dir ? b_b_hh  : f_b_hh;
    const float* deltas = dir ? deltas_b : deltas_f;

    __shared__ __align__(16) float s_hd[128];   // decayed hidden; [108..127] = 0 pad
    __shared__ float s_gates[G4];               // s_gates[g*108+j]
    __shared__ float s_scalar[2];               // {x_c, m}
    __shared__ float s_par[12][H];              // input weights / fused biases, SoA
    __shared__ float s_c[H];                    // cell state
    __shared__ float s_tdw[H], s_tdb[H];
    __shared__ float s_gamma[H];                // next-step decay factors

    const int tid  = threadIdx.x;
    const int lane = tid & 31;
    const int j    = tid >> 3;      // unit index (gate threads)
    const int kc   = tid & 7;       // K-chunk index

    // ---- one-time init: 4 gate rows x KC weights in registers (28 x f32x2) ----
    unsigned long long w[28];
    if (tid < NGATE) {
        #pragma unroll
        for (int g = 0; g < 4; g++) {
            const float* rw = W_hh + (g * H + j) * H;
            #pragma unroll
            for (int i = 0; i < 7; i++) {
                int k = KC * kc + 2 * i;
                float a = (k     < H) ? rw[k]     : 0.0f;
                float b = (k + 1 < H) ? rw[k + 1] : 0.0f;
                w[g * 7 + i] = pk2(a, b);
            }
        }
    } else {
        #pragma unroll
        for (int i = 0; i < 28; i++) w[i] = 0ull;
    }

    // s_par[kind*4+q][u]: kind0=W_ih[:,0], kind1=W_ih[:,1], kind2=b_ih+b_hh; row r=q*H+u
    for (int k = tid; k < 12 * H; k += NTHR) {
        int u = k % H;
        int f = k / H;
        int q = f & 3;
        int kind = f >> 2;
        int r = q * H + u;
        float v;
        if (kind == 0)      v = W_ih[2 * r];
        else if (kind == 1) v = W_ih[2 * r + 1];
        else                v = b_ih[r] + b_hh[r];
        s_par[f][u] = v;
    }

    if (tid < H) {
        s_c[tid]   = 0.0f;
        s_tdw[tid] = td_w[tid];
        s_tdb[tid] = td_b[tid];
    }
    if (tid < 128) s_hd[tid] = 0.0f;

    float loss = 0.0f, lcomp = 0.0f;   // scalar warp lane 0 only
    __syncthreads();

    const uint32_t hd_smem = (uint32_t)__cvta_generic_to_shared(s_hd);
    const uint32_t haddr   = hd_smem + (uint32_t)(4 * KC * kc);   // 56B per chunk

    for (int t = 0; t < T_LEN; ++t) {
        const int idx = dir ? (T_LEN - 1 - t) : t;

        if (tid < NGATE) {
            // ---- phase A: 4-row x 14-K partial dot; each h load feeds 4 FMAs ----
            unsigned long long a0 = 0ull, a1 = 0ull, a2 = 0ull, a3 = 0ull;
            #pragma unroll
            for (int i = 0; i < 7; i++) {
                unsigned long long hp;
                asm volatile("ld.shared.u64 %0, [%1];" : "=l"(hp) : "r"(haddr + 8u * i));
                fma2(a0, w[i],      hp);
                fma2(a1, w[7 + i],  hp);
                fma2(a2, w[14 + i], hp);
                fma2(a3, w[21 + i], hp);
            }
            float2 p0 = upk(a0), p1 = upk(a1), p2 = upk(a2), p3 = upk(a3);
            float s0 = p0.x + p0.y, s1 = p1.x + p1.y, s2 = p2.x + p2.y, s3 = p3.x + p3.y;
            // butterfly over the 8-lane kc-group
            #pragma unroll
            for (int o = 1; o < 8; o <<= 1) {
                s0 += __shfl_xor_sync(0xffffffffu, s0, o);
                s1 += __shfl_xor_sync(0xffffffffu, s1, o);
                s2 += __shfl_xor_sync(0xffffffffu, s2, o);
                s3 += __shfl_xor_sync(0xffffffffu, s3, o);
            }
            if (kc < 4) {
                float v = (kc == 0) ? s0 : (kc == 1) ? s1 : (kc == 2) ? s2 : s3;
                s_gates[kc * H + j] = v;
            }
        } else {
            // ---- scalar warp: x_h dot, loss, imputation, and next-step gamma ----
            float p = reg_w[lane] * s_hd[lane]
                    + ((lane + 32 < H) ? reg_w[lane + 32] * s_hd[lane + 32] : 0.0f)
                    + ((lane + 64 < H) ? reg_w[lane + 64] * s_hd[lane + 64] : 0.0f)
                    + ((lane + 96 < H) ? reg_w[lane + 96] * s_hd[lane + 96] : 0.0f);
            #pragma unroll
            for (int o = 16; o > 0; o >>= 1) p += __shfl_xor_sync(0xffffffffu, p, o);

            // gamma for t+1 (depends only on deltas/params -> computed here, hidden)
            int tn = (t + 1 < T_LEN) ? (t + 1) : (T_LEN - 1);
            float dn = deltas[tn];
            #pragma unroll
            for (int q = 0; q < 4; q++) {
                int u = lane + 32 * q;
                if (u < H) {
                    float e = fmaxf(fmaf(dn, s_tdw[u], s_tdb[u]), 0.0f);
                    s_gamma[u] = __expf(-e);
                }
            }

            if (lane == 0) {
                float xv = values[idx], m = masks[idx];
                float x_h = p + reg_b[0];
                float x_c = m * xv + (1.0f - m) * x_h;
                float term = fabsf(xv - x_h) * m / (m + 1e-5f);
                float y = term - lcomp;
                float ts = loss + y;
                lcomp = (ts - loss) - y;
                loss = ts;
                g_imp[dir][idx] = x_c;
                s_scalar[0] = x_c;
                s_scalar[1] = m;
            }
        }
        __syncthreads();

        // ---- phase B: pointwise LSTM cell (dense threads 0..107) ----
        if (tid < H) {
            const int u = tid;
            float cprev = s_c[u];
            float gam   = s_gamma[u];
            float xc = s_scalar[0], m = s_scalar[1];
            float gi = fmaf(s_par[0][u], xc, fmaf(s_par[4][u], m, s_gates[u]          + s_par[8][u]));
            float gf = fmaf(s_par[1][u], xc, fmaf(s_par[5][u], m, s_gates[H + u]      + s_par[9][u]));
            float gg = fmaf(s_par[2][u], xc, fmaf(s_par[6][u], m, s_gates[2 * H + u]  + s_par[10][u]));
            float go = fmaf(s_par[3][u], xc, fmaf(s_par[7][u], m, s_gates[3 * H + u]  + s_par[11][u]));
            float si = sigmoid_fast(gi);
            float sf = sigmoid_fast(gf);
            float so = sigmoid_fast(go);
            float tg = tanh_fast(gg);
            float c  = sf * cprev + si * tg;
            s_c[u] = c;
            float hh = so * tanh_fast(c);
            s_hd[u] = hh * gam;              // decay for t+1 already folded in
        }
        __syncthreads();
    }

    if (tid == NGATE) g_loss[dir] = loss;
}

// ---------------- combine + finalize ----------------
__global__ void combine_kernel(float* __restrict__ out)
{
    __shared__ float red[256];
    const int i = blockIdx.x * 256 + threadIdx.x;
    float a = g_imp[0][i];
    float b = g_imp[1][i];
    out[1 + i] = 0.5f * (a + b);
    red[threadIdx.x] = fabsf(a - b);
    __syncthreads();
    #pragma unroll
    for (int s = 128; s > 0; s >>= 1) {
        if (threadIdx.x < s) red[threadIdx.x] += red[threadIdx.x + s];
        __syncthreads();
    }
    if (threadIdx.x == 0) g_part[blockIdx.x] = red[0];
}

__global__ void finalize_kernel(float* __restrict__ out)
{
    __shared__ float red[256];
    red[threadIdx.x] = g_part[threadIdx.x];
    __syncthreads();
    #pragma unroll
    for (int s = 128; s > 0; s >>= 1) {
        if (threadIdx.x < s) red[threadIdx.x] += red[threadIdx.x + s];
        __syncthreads();
    }
    if (threadIdx.x == 0) {
        float loss_c = red[0] / (float)T_LEN;
        out[0] = 0.3f * (g_loss[0] + g_loss[1]) + loss_c;
    }
}

// ---------------- launch ----------------
extern "C" void kernel_launch(void* const* d_in, const int* in_sizes, int n_in,
                              void* d_out, int out_size)
{
    (void)in_sizes; (void)n_in; (void)out_size;
    const float* values   = (const float*)d_in[0];
    const float* masks    = (const float*)d_in[1];
    const float* deltas_f = (const float*)d_in[2];
    const float* deltas_b = (const float*)d_in[3];
    const float* f_td_w   = (const float*)d_in[4];
    const float* f_td_b   = (const float*)d_in[5];
    const float* f_reg_w  = (const float*)d_in[6];
    const float* f_reg_b  = (const float*)d_in[7];
    const float* f_W_ih   = (const float*)d_in[8];
    const float* f_W_hh   = (const float*)d_in[9];
    const float* f_b_ih   = (const float*)d_in[10];
    const float* f_b_hh   = (const float*)d_in[11];
    const float* b_td_w   = (const float*)d_in[12];
    const float* b_td_b   = (const float*)d_in[13];
    const float* b_reg_w  = (const float*)d_in[14];
    const float* b_reg_b  = (const float*)d_in[15];
    const float* b_W_ih   = (const float*)d_in[16];
    const float* b_W_hh   = (const float*)d_in[17];
    const float* b_b_ih   = (const float*)d_in[18];
    const float* b_b_hh   = (const float*)d_in[19];
    float* out = (float*)d_out;

    brits_kernel<<<2, NTHR>>>(values, masks, deltas_f, deltas_b,
                              f_td_w, f_td_b, f_reg_w, f_reg_b, f_W_ih, f_W_hh, f_b_ih, f_b_hh,
                              b_td_w, b_td_b, b_reg_w, b_reg_b, b_W_ih, b_W_hh, b_b_ih, b_b_hh);
    combine_kernel<<<T_LEN / 256, 256>>>(out);
    finalize_kernel<<<1, 256>>>(out);
}